// round 12
// baseline (speedup 1.0000x reference)
#include <cuda_runtime.h>
#include <cuda_bf16.h>
#include <cstdint>
#include <math.h>

// ---------------------------------------------------------------------------
// minGRU forward on GB300.
// hg = W @ x + b via a HYBRID GEMM: per-CTA role split between
//   - tf32 mma.sync path (tensor pipe, at its rt~16 issue floor), n-tiles [0,44)
//   - packed fp32 FFMA2 path (fma pipe, exact), n-tiles [44,64)
// The two roles use disjoint execution pipes and overlap when co-resident.
// Then per-(b,h) linear scan h_t = c_t h_{t-1} + v_t.
// ---------------------------------------------------------------------------

#define Bsz 8
#define Dd  512
#define Hh  512
#define Ll  8192
#define TWOH 1024

// Scratch (device globals: allocation-free path)
__device__ float g_hg [(size_t)Bsz * TWOH * Ll];   // 268 MB
__device__ float g_x32[(size_t)Bsz * Ll * Dd];     // 134 MB [B,L,D] tf32 (tensor range only)
__device__ float g_w32[(size_t)TWOH * Dd];         // 2 MB   [2H,D]  tf32-rounded

// ---------------------------- PTX helpers ----------------------------------
__device__ __forceinline__ uint32_t smem_u32(const void* p) {
    uint32_t a;
    asm("{ .reg .u64 t; cvta.to.shared.u64 t, %1; cvt.u32.u64 %0, t; }"
        : "=r"(a) : "l"(p));
    return a;
}
#define SW128(o) ((o) ^ (((o) >> 3) & 0x70))

__device__ __forceinline__ void cp16(uint32_t dst, const void* src) {
    asm volatile("cp.async.cg.shared.global [%0], [%1], 16;"
                 :: "r"(dst), "l"(__cvta_generic_to_global(src)) : "memory");
}
#define CP_COMMIT() asm volatile("cp.async.commit_group;" ::: "memory")
#define CP_WAIT0()  asm volatile("cp.async.wait_group 0;" ::: "memory")
#define CP_WAIT1()  asm volatile("cp.async.wait_group 1;" ::: "memory")

__device__ __forceinline__ void ldsm_x4(uint32_t &r0, uint32_t &r1,
                                        uint32_t &r2, uint32_t &r3,
                                        uint32_t addr) {
    asm volatile("ldmatrix.sync.aligned.m8n8.x4.shared.b16 {%0,%1,%2,%3}, [%4];"
                 : "=r"(r0), "=r"(r1), "=r"(r2), "=r"(r3) : "r"(addr));
}

__device__ __forceinline__ void mma_tf32(float c[4], const uint32_t a[4],
                                         const uint32_t b[2]) {
    asm volatile(
        "mma.sync.aligned.m16n8k8.row.col.f32.tf32.tf32.f32 "
        "{%0,%1,%2,%3}, {%4,%5,%6,%7}, {%8,%9}, {%0,%1,%2,%3};"
        : "+f"(c[0]), "+f"(c[1]), "+f"(c[2]), "+f"(c[3])
        : "r"(a[0]), "r"(a[1]), "r"(a[2]), "r"(a[3]), "r"(b[0]), "r"(b[1]));
}

__device__ __forceinline__ float tf32r(float x) {
    uint32_t u;
    asm("cvt.rna.tf32.f32 %0, %1;" : "=r"(u) : "f"(x));
    return __uint_as_float(u);
}

// packed f32x2 helpers (double-rate FMA on the fma pipe)
__device__ __forceinline__ unsigned long long pack2(float x, float y) {
    unsigned long long r;
    asm("mov.b64 %0, {%1, %2};" : "=l"(r) : "f"(x), "f"(y));
    return r;
}
__device__ __forceinline__ void unpack2(unsigned long long p, float &x, float &y) {
    asm("mov.b64 {%0, %1}, %2;" : "=f"(x), "=f"(y) : "l"(p));
}
__device__ __forceinline__ void ffma2(unsigned long long &d,
                                      unsigned long long a,
                                      unsigned long long b) {
    asm("fma.rn.f32x2 %0, %1, %2, %0;" : "+l"(d) : "l"(a), "l"(b));
}

// ---------------------------------------------------------------------------
// Tiling / role split
// ---------------------------------------------------------------------------
#define BM 128
#define BN 128
#define NT_TILES 44                 // tensor n-tiles; fma handles the rest (20)
#define N_T (NT_TILES * BN)         // 5632

// tensor path constants
#define BK 32
#define NCHUNK (Dd / BK)            // 16
#define NSTAGE 3
#define TILE_B (BM * 128)           // 16 KB
#define STG    (2 * TILE_B)         // 32 KB / stage
#define SMEM_BYTES (NSTAGE * STG + 1024)   // 99328

// fma path constants
#define FBK 16

// ---------------------------------------------------------------------------
// Prep kernels
// ---------------------------------------------------------------------------
__global__ void round_w_kernel(const float* __restrict__ W) {
    int i = (blockIdx.x * 256 + threadIdx.x) * 4;
    float4 v = *(const float4*)(W + i);
    v.x = tf32r(v.x); v.y = tf32r(v.y); v.z = tf32r(v.z); v.w = tf32r(v.w);
    *(float4*)&g_w32[i] = v;
}

// Transpose+round X: [B, D, L] -> [B, L, D] tf32, only l < N_T (tensor range)
__global__ __launch_bounds__(256)
void trans_x_kernel(const float* __restrict__ X) {
    __shared__ float ts[64 * 65];
    const int b  = blockIdx.z;
    const int d0 = blockIdx.y * 64;
    const int l0 = blockIdx.x * 64;
    const int t  = threadIdx.x;

    {
        const int dl = t >> 2;
        const int lc = (t & 3) * 16;
        const float* src = X + ((size_t)b * Dd + d0 + dl) * Ll + l0 + lc;
        #pragma unroll
        for (int j = 0; j < 4; j++) {
            float4 v = *(const float4*)(src + j * 4);
            ts[dl * 65 + lc + j * 4 + 0] = v.x;
            ts[dl * 65 + lc + j * 4 + 1] = v.y;
            ts[dl * 65 + lc + j * 4 + 2] = v.z;
            ts[dl * 65 + lc + j * 4 + 3] = v.w;
        }
    }
    __syncthreads();

    const int ll = t >> 2;
    const int dc = (t & 3) * 16;
    float* dst = g_x32 + ((size_t)b * Ll + l0 + ll) * Dd + d0 + dc;
    #pragma unroll
    for (int q = 0; q < 4; q++) {
        float4 o;
        o.x = tf32r(ts[(dc + q * 4 + 0) * 65 + ll]);
        o.y = tf32r(ts[(dc + q * 4 + 1) * 65 + ll]);
        o.z = tf32r(ts[(dc + q * 4 + 2) * 65 + ll]);
        o.w = tf32r(ts[(dc + q * 4 + 3) * 65 + ll]);
        *(float4*)(dst + q * 4) = o;
    }
}

// ---------------------------------------------------------------------------
// Hybrid GEMM kernel
// ---------------------------------------------------------------------------
__global__ __launch_bounds__(256, 2)
void gemm_hybrid_kernel(const float* __restrict__ X,
                        const float* __restrict__ W,
                        const float* __restrict__ bias) {
    extern __shared__ char dynsmem[];
    const int tid  = threadIdx.x;
    const int bz = blockIdx.z;
    const int m0 = blockIdx.y * BM;
    const int n0 = blockIdx.x * BN;

    if (blockIdx.x < NT_TILES) {
        // =================== TENSOR ROLE (tf32 mma.sync, R9-proven) =========
        const uint32_t S = (smem_u32(dynsmem) + 1023u) & ~1023u;
        const int wid  = tid >> 5;
        const int lane = tid & 31;

        const int lrow  = tid >> 1;
        const int lhalf = (tid & 1) * 4;
        const float* srcA = g_w32 + (size_t)(m0 + lrow) * Dd;
        const float* srcB = g_x32 + ((size_t)bz * Ll + n0 + lrow) * Dd;

        #define ISSUE_CHUNK(kc)                                                 \
        do {                                                                    \
            const int _st = (kc) % NSTAGE;                                     \
            const uint32_t _sA = S + _st * STG;                                 \
            const uint32_t _sB = _sA + TILE_B;                                  \
            const int _kb = (kc) * 128;                                         \
            _Pragma("unroll")                                                   \
            for (int j = 0; j < 4; j++) {                                       \
                const int jj = lhalf + j;                                       \
                const uint32_t so = SW128((uint32_t)(lrow * 128 + jj * 16));    \
                cp16(_sA + so, (const char*)srcA + _kb + jj * 16);              \
                cp16(_sB + so, (const char*)srcB + _kb + jj * 16);              \
            }                                                                   \
            CP_COMMIT();                                                        \
        } while (0)

        const int mw = (wid & 3) * 32;
        const int nw = (wid >> 2) * 64;
        const int aRow     = lane & 15;
        const int aColByte = (lane >> 4) * 16;
        const int bRow     = (lane & 7) + ((lane >> 4) << 3);
        const int bColByte = ((lane >> 3) & 1) * 16;

        uint32_t aByte[2], bByte[4];
        #pragma unroll
        for (int i = 0; i < 2; i++)
            aByte[i] = (uint32_t)((mw + i * 16 + aRow) * 128 + aColByte);
        #pragma unroll
        for (int p = 0; p < 4; p++)
            bByte[p] = (uint32_t)((nw + p * 16 + bRow) * 128 + bColByte);

        float acc[2][8][4];
        #pragma unroll
        for (int i = 0; i < 2; i++)
            #pragma unroll
            for (int j = 0; j < 8; j++)
                #pragma unroll
                for (int q = 0; q < 4; q++) acc[i][j][q] = 0.0f;

        ISSUE_CHUNK(0);
        ISSUE_CHUNK(1);

        for (int kc = 0; kc < NCHUNK; kc++) {
            if (kc == NCHUNK - 1) CP_WAIT0(); else CP_WAIT1();
            __syncthreads();

            if (kc + 2 < NCHUNK) ISSUE_CHUNK(kc + 2);

            const int st = kc % NSTAGE;
            const uint32_t sA = S + st * STG;
            const uint32_t sB = sA + TILE_B;

            #pragma unroll
            for (int ks = 0; ks < 4; ks++) {
                uint32_t a[2][4];
                #pragma unroll
                for (int i = 0; i < 2; i++)
                    ldsm_x4(a[i][0], a[i][1], a[i][2], a[i][3],
                            sA + SW128(aByte[i] + ks * 32));
                uint32_t b[8][2];
                #pragma unroll
                for (int p = 0; p < 4; p++)
                    ldsm_x4(b[2*p][0], b[2*p][1], b[2*p+1][0], b[2*p+1][1],
                            sB + SW128(bByte[p] + ks * 32));
                #pragma unroll
                for (int i = 0; i < 2; i++)
                    #pragma unroll
                    for (int j = 0; j < 8; j++)
                        mma_tf32(acc[i][j], a[i], b[j]);
            }
            __syncthreads();
        }

        const int mrow = m0 + mw + (lane >> 2);
        const int ncol = n0 + nw + (lane & 3) * 2;
        #pragma unroll
        for (int i = 0; i < 2; i++) {
            const int r0 = mrow + i * 16;
            const float b0 = bias[r0];
            const float b1 = bias[r0 + 8];
            float* C0 = g_hg + ((size_t)bz * TWOH + r0)     * Ll;
            float* C1 = g_hg + ((size_t)bz * TWOH + r0 + 8) * Ll;
            #pragma unroll
            for (int j = 0; j < 8; j++) {
                const int c = ncol + j * 8;
                float2 o0 = { acc[i][j][0] + b0, acc[i][j][1] + b0 };
                float2 o1 = { acc[i][j][2] + b1, acc[i][j][3] + b1 };
                *(float2*)(C0 + c) = o0;
                *(float2*)(C1 + c) = o1;
            }
        }
    } else {
        // =================== FMA ROLE (packed FFMA2, R5-proven, exact) ======
        float* As = (float*)dynsmem;            // [FBK][BM+4]
        float* Bs = As + FBK * (BM + 4);        // [FBK][BN]

        const float* Xb = X + (size_t)bz * Dd * Ll;
        float*       C  = g_hg + (size_t)bz * TWOH * Ll;

        const int ty  = tid >> 4;
        const int tx  = tid & 15;
        const int ar  = tid >> 2;
        const int ac  = (tid & 3) * 4;
        const int br  = tid >> 4;
        const int bc  = (tid & 15) * 4;

        unsigned long long acc[8][4];
        #pragma unroll
        for (int i = 0; i < 8; i++)
            #pragma unroll
            for (int j = 0; j < 4; j++) acc[i][j] = 0ULL;

        for (int k0 = 0; k0 < Dd; k0 += FBK) {
            float4 a0 = *(const float4*)(W  + (size_t)(m0 + ar)      * Dd + k0 + ac);
            float4 a1 = *(const float4*)(W  + (size_t)(m0 + 64 + ar) * Dd + k0 + ac);
            float4 b0 = *(const float4*)(Xb + (size_t)(k0 + br) * Ll + n0 + bc);
            float4 b1 = *(const float4*)(Xb + (size_t)(k0 + br) * Ll + n0 + bc + 64);

            __syncthreads();
            As[(ac + 0) * (BM + 4) + ar]      = a0.x;
            As[(ac + 1) * (BM + 4) + ar]      = a0.y;
            As[(ac + 2) * (BM + 4) + ar]      = a0.z;
            As[(ac + 3) * (BM + 4) + ar]      = a0.w;
            As[(ac + 0) * (BM + 4) + 64 + ar] = a1.x;
            As[(ac + 1) * (BM + 4) + 64 + ar] = a1.y;
            As[(ac + 2) * (BM + 4) + 64 + ar] = a1.z;
            As[(ac + 3) * (BM + 4) + 64 + ar] = a1.w;
            *(float4*)&Bs[br * BN + bc]      = b0;
            *(float4*)&Bs[br * BN + bc + 64] = b1;
            __syncthreads();

            #pragma unroll
            for (int kk = 0; kk < FBK; kk++) {
                float4 af0 = *(const float4*)&As[kk * (BM + 4) + ty * 4];
                float4 af1 = *(const float4*)&As[kk * (BM + 4) + 64 + ty * 4];
                float4 bf0 = *(const float4*)&Bs[kk * BN + tx * 4];
                float4 bf1 = *(const float4*)&Bs[kk * BN + 64 + tx * 4];

                unsigned long long bp[4];
                bp[0] = pack2(bf0.x, bf0.y);
                bp[1] = pack2(bf0.z, bf0.w);
                bp[2] = pack2(bf1.x, bf1.y);
                bp[3] = pack2(bf1.z, bf1.w);

                float am[8] = {af0.x, af0.y, af0.z, af0.w,
                               af1.x, af1.y, af1.z, af1.w};
                #pragma unroll
                for (int i = 0; i < 8; i++) {
                    unsigned long long ad = pack2(am[i], am[i]);
                    #pragma unroll
                    for (int j = 0; j < 4; j++) ffma2(acc[i][j], ad, bp[j]);
                }
            }
        }

        #pragma unroll
        for (int i = 0; i < 8; i++) {
            const int m  = m0 + ((i < 4) ? (ty * 4 + i) : (64 + ty * 4 + i - 4));
            const float bb = bias[m];
            float* Crow = C + (size_t)m * Ll + n0;
            float4 o;
            unpack2(acc[i][0], o.x, o.y);
            unpack2(acc[i][1], o.z, o.w);
            o.x += bb; o.y += bb; o.z += bb; o.w += bb;
            *(float4*)(Crow + tx * 4) = o;
            unpack2(acc[i][2], o.x, o.y);
            unpack2(acc[i][3], o.z, o.w);
            o.x += bb; o.y += bb; o.z += bb; o.w += bb;
            *(float4*)(Crow + 64 + tx * 4) = o;
        }
    }
}

// ---------------------------------------------------------------------------
// Scan: one block per (b,h) lane; 2 blocks/SM; fast-math exp.
// ---------------------------------------------------------------------------
__global__ __launch_bounds__(1024, 2)
void scan_kernel(float* __restrict__ out) {
    const int lane_id = blockIdx.x;
    const int b = lane_id >> 9;
    const int h = lane_id & 511;

    const float* Hrow = g_hg + ((size_t)b * TWOH + h)      * Ll;
    const float* Grow = g_hg + ((size_t)b * TWOH + Hh + h) * Ll;
    float*       Orow = out  + (size_t)lane_id * Ll;

    const int t  = threadIdx.x;
    const int l0 = t * 8;

    float4 hA = *(const float4*)(Hrow + l0);
    float4 hB = *(const float4*)(Hrow + l0 + 4);
    float4 gA = *(const float4*)(Grow + l0);
    float4 gB = *(const float4*)(Grow + l0 + 4);

    float hv[8] = {hA.x, hA.y, hA.z, hA.w, hB.x, hB.y, hB.z, hB.w};
    float gv[8] = {gA.x, gA.y, gA.z, gA.w, gB.x, gB.y, gB.z, gB.w};

    float c[8], v[8];
    #pragma unroll
    for (int i = 0; i < 8; i++) {
        const float g  = gv[i];
        const float eg = __expf(g);
        const float ci = 1.0f / (1.0f + eg);          // sigmoid(-g)
        const float si = 1.0f - ci;                   // sigmoid(g)
        const float z  = hv[i];
        const float gf = (z >= 0.0f) ? (z + 1.0f) : __expf(z);
        c[i] = ci;
        v[i] = si * gf;
    }

    float C = c[0], V = v[0];
    #pragma unroll
    for (int i = 1; i < 8; i++) {
        V = fmaf(c[i], V, v[i]);
        C *= c[i];
    }

    const int lane = t & 31, warp = t >> 5;
    #pragma unroll
    for (int d = 1; d < 32; d <<= 1) {
        float Cp = __shfl_up_sync(0xFFFFFFFFu, C, d);
        float Vp = __shfl_up_sync(0xFFFFFFFFu, V, d);
        if (lane >= d) { V = fmaf(C, Vp, V); C = C * Cp; }
    }

    __shared__ float sC[32], sV[32];
    if (lane == 31) { sC[warp] = C; sV[warp] = V; }
    __syncthreads();

    if (warp == 0) {
        float Cw = sC[lane], Vw = sV[lane];
        #pragma unroll
        for (int d = 1; d < 32; d <<= 1) {
            float Cp = __shfl_up_sync(0xFFFFFFFFu, Cw, d);
            float Vp = __shfl_up_sync(0xFFFFFFFFu, Vw, d);
            if (lane >= d) { Vw = fmaf(Cw, Vp, Vw); Cw = Cw * Cp; }
        }
        sC[lane] = Cw;
        sV[lane] = Vw;
    }
    __syncthreads();

    float bV = (warp == 0) ? 0.0f : sV[warp - 1];

    float eC = __shfl_up_sync(0xFFFFFFFFu, C, 1);
    float eV = __shfl_up_sync(0xFFFFFFFFu, V, 1);
    if (lane == 0) { eC = 1.0f; eV = 0.0f; }

    float acc = fmaf(eC, bV, eV);

    float o[8];
    #pragma unroll
    for (int i = 0; i < 8; i++) {
        acc  = fmaf(c[i], acc, v[i]);
        o[i] = acc;
    }
    float4 oA = {o[0], o[1], o[2], o[3]};
    float4 oB = {o[4], o[5], o[6], o[7]};
    *(float4*)(Orow + l0)     = oA;
    *(float4*)(Orow + l0 + 4) = oB;
}

// ---------------------------------------------------------------------------
extern "C" void kernel_launch(void* const* d_in, const int* in_sizes, int n_in,
                              void* d_out, int out_size) {
    const float* x = nullptr;
    const float* W = nullptr;
    const float* bias = nullptr;
    for (int i = 0; i < n_in; i++) {
        const int s = in_sizes[i];
        if      (s == Bsz * Dd * Ll) x    = (const float*)d_in[i];
        else if (s == TWOH * Dd)     W    = (const float*)d_in[i];
        else if (s == TWOH)          bias = (const float*)d_in[i];
    }

    static int smem_set = 0;
    if (!smem_set) {
        cudaFuncSetAttribute(gemm_hybrid_kernel,
                             cudaFuncAttributeMaxDynamicSharedMemorySize,
                             SMEM_BYTES);
        smem_set = 1;
    }

    round_w_kernel<<<TWOH * Dd / (256 * 4), 256>>>(W);
    trans_x_kernel<<<dim3(N_T / 64, Dd / 64, Bsz), 256>>>(x);   // tensor range only
    gemm_hybrid_kernel<<<dim3(Ll / BN, TWOH / BM, Bsz), 256, SMEM_BYTES>>>(x, W, bias);
    scan_kernel<<<Bsz * Hh, 1024>>>((float*)d_out);
}

// round 13
// speedup vs baseline: 1.4124x; 1.4124x over previous
#include <cuda_runtime.h>
#include <cuda_bf16.h>
#include <cstdint>
#include <math.h>

// ---------------------------------------------------------------------------
// minGRU forward on GB300 (compute_103 PTX => classic mma.sync tensor path):
//   hg = W @ x + b   via single-pass TF32 mma.sync GEMM (R9 structure, at the
//                    legacy-HMMA issue floor), redundant end-of-loop barrier
//                    removed.
//   then per-(b,h) linear scan  h_t = c_t h_{t-1} + v_t   (fast-exp, 2/SM)
// ---------------------------------------------------------------------------

#define Bsz 8
#define Dd  512
#define Hh  512
#define Ll  8192
#define TWOH 1024

// Scratch (device globals: allocation-free path)
__device__ float g_hg [(size_t)Bsz * TWOH * Ll];   // 268 MB
__device__ float g_x32[(size_t)Bsz * Ll * Dd];     // 134 MB  [B,L,D] tf32-rounded
__device__ float g_w32[(size_t)TWOH * Dd];         // 2 MB    [2H,D]  tf32-rounded

// ---------------------------- PTX helpers ----------------------------------
__device__ __forceinline__ uint32_t smem_u32(const void* p) {
    uint32_t a;
    asm("{ .reg .u64 t; cvta.to.shared.u64 t, %1; cvt.u32.u64 %0, t; }"
        : "=r"(a) : "l"(p));
    return a;
}
#define SW128(o) ((o) ^ (((o) >> 3) & 0x70))

__device__ __forceinline__ void cp16(uint32_t dst, const void* src) {
    asm volatile("cp.async.cg.shared.global [%0], [%1], 16;"
                 :: "r"(dst), "l"(__cvta_generic_to_global(src)) : "memory");
}
#define CP_COMMIT() asm volatile("cp.async.commit_group;" ::: "memory")
#define CP_WAIT0()  asm volatile("cp.async.wait_group 0;" ::: "memory")
#define CP_WAIT1()  asm volatile("cp.async.wait_group 1;" ::: "memory")

__device__ __forceinline__ void ldsm_x4(uint32_t &r0, uint32_t &r1,
                                        uint32_t &r2, uint32_t &r3,
                                        uint32_t addr) {
    asm volatile("ldmatrix.sync.aligned.m8n8.x4.shared.b16 {%0,%1,%2,%3}, [%4];"
                 : "=r"(r0), "=r"(r1), "=r"(r2), "=r"(r3) : "r"(addr));
}

__device__ __forceinline__ void mma_tf32(float c[4], const uint32_t a[4],
                                         const uint32_t b[2]) {
    asm volatile(
        "mma.sync.aligned.m16n8k8.row.col.f32.tf32.tf32.f32 "
        "{%0,%1,%2,%3}, {%4,%5,%6,%7}, {%8,%9}, {%0,%1,%2,%3};"
        : "+f"(c[0]), "+f"(c[1]), "+f"(c[2]), "+f"(c[3])
        : "r"(a[0]), "r"(a[1]), "r"(a[2]), "r"(a[3]), "r"(b[0]), "r"(b[1]));
}

__device__ __forceinline__ float tf32r(float x) {
    uint32_t u;
    asm("cvt.rna.tf32.f32 %0, %1;" : "=r"(u) : "f"(x));
    return __uint_as_float(u);
}

// ---------------------------------------------------------------------------
// Prep kernels: round W to tf32; transpose+round X [B,D,L] -> [B,L,D]
// ---------------------------------------------------------------------------
__global__ void round_w_kernel(const float* __restrict__ W) {
    int i = (blockIdx.x * 256 + threadIdx.x) * 4;
    float4 v = *(const float4*)(W + i);
    v.x = tf32r(v.x); v.y = tf32r(v.y); v.z = tf32r(v.z); v.w = tf32r(v.w);
    *(float4*)&g_w32[i] = v;
}

__global__ __launch_bounds__(256)
void trans_x_kernel(const float* __restrict__ X) {
    __shared__ float ts[64 * 65];
    const int b  = blockIdx.z;
    const int d0 = blockIdx.y * 64;
    const int l0 = blockIdx.x * 64;
    const int t  = threadIdx.x;

    {
        const int dl = t >> 2;
        const int lc = (t & 3) * 16;
        const float* src = X + ((size_t)b * Dd + d0 + dl) * Ll + l0 + lc;
        #pragma unroll
        for (int j = 0; j < 4; j++) {
            float4 v = *(const float4*)(src + j * 4);
            ts[dl * 65 + lc + j * 4 + 0] = v.x;
            ts[dl * 65 + lc + j * 4 + 1] = v.y;
            ts[dl * 65 + lc + j * 4 + 2] = v.z;
            ts[dl * 65 + lc + j * 4 + 3] = v.w;
        }
    }
    __syncthreads();

    const int ll = t >> 2;
    const int dc = (t & 3) * 16;
    float* dst = g_x32 + ((size_t)b * Ll + l0 + ll) * Dd + d0 + dc;
    #pragma unroll
    for (int q = 0; q < 4; q++) {
        float4 o;
        o.x = tf32r(ts[(dc + q * 4 + 0) * 65 + ll]);
        o.y = tf32r(ts[(dc + q * 4 + 1) * 65 + ll]);
        o.z = tf32r(ts[(dc + q * 4 + 2) * 65 + ll]);
        o.w = tf32r(ts[(dc + q * 4 + 3) * 65 + ll]);
        *(float4*)(dst + q * 4) = o;
    }
}

// ---------------------------------------------------------------------------
// TF32 mma.sync GEMM: C[b](1024 x 8192) = W(1024x512) @ X[b]^T + bias
// BM=128, BN=128, BK=32, 3-stage cp.async pipeline, SW128 swizzle,
// 8 warps (4M x 2N), warp tile 32x64, 2 CTAs/SM. One barrier per k-chunk
// (top-of-iteration sync already orders stage reuse at NSTAGE=3).
// ---------------------------------------------------------------------------
#define BM 128
#define BN 128
#define BK 32
#define NCHUNK (Dd / BK)       // 16
#define NSTAGE 3
#define TILE_B (BM * 128)      // 16 KB per operand tile (128B rows)
#define STG    (2 * TILE_B)    // A + B per stage = 32 KB
#define SMEM_BYTES (NSTAGE * STG + 1024)   // 99328

__global__ __launch_bounds__(256, 2)
void gemm_tc_kernel(const float* __restrict__ bias) {
    extern __shared__ char dynsmem[];
    const uint32_t S = (smem_u32(dynsmem) + 1023u) & ~1023u;

    const int tid  = threadIdx.x;
    const int wid  = tid >> 5;
    const int lane = tid & 31;
    const int bz = blockIdx.z;
    const int m0 = blockIdx.x * BM;
    const int n0 = blockIdx.y * BN;

    // ---- load mapping: 2 threads per 128B row, 4x cp16 each per operand ----
    const int lrow  = tid >> 1;           // 0..127
    const int lhalf = (tid & 1) * 4;      // 0 or 4

    const float* srcA = g_w32 + (size_t)(m0 + lrow) * Dd;
    const float* srcB = g_x32 + ((size_t)bz * Ll + n0 + lrow) * Dd;

    #define ISSUE_CHUNK(kc)                                                     \
    do {                                                                        \
        const int _st = (kc) % NSTAGE;                                          \
        const uint32_t _sA = S + _st * STG;                                     \
        const uint32_t _sB = _sA + TILE_B;                                      \
        const int _kb = (kc) * 128;  /* BK*4 bytes into the source row */       \
        _Pragma("unroll")                                                       \
        for (int j = 0; j < 4; j++) {                                           \
            const int jj = lhalf + j;                                           \
            const uint32_t so = SW128((uint32_t)(lrow * 128 + jj * 16));        \
            cp16(_sA + so, (const char*)srcA + _kb + jj * 16);                  \
            cp16(_sB + so, (const char*)srcB + _kb + jj * 16);                  \
        }                                                                       \
        CP_COMMIT();                                                            \
    } while (0)

    // ---- fragment lane addressing (tf32 via ldmatrix.b16 on 8x4-fp32) ----
    const int mw = (wid & 3) * 32;        // warp M offset
    const int nw = (wid >> 2) * 64;       // warp N offset
    const int aRow     = lane & 15;
    const int aColByte = (lane >> 4) * 16;
    const int bRow     = (lane & 7) + ((lane >> 4) << 3);
    const int bColByte = ((lane >> 3) & 1) * 16;

    uint32_t aByte[2], bByte[4];
    #pragma unroll
    for (int i = 0; i < 2; i++)
        aByte[i] = (uint32_t)((mw + i * 16 + aRow) * 128 + aColByte);
    #pragma unroll
    for (int p = 0; p < 4; p++)
        bByte[p] = (uint32_t)((nw + p * 16 + bRow) * 128 + bColByte);

    float acc[2][8][4];
    #pragma unroll
    for (int i = 0; i < 2; i++)
        #pragma unroll
        for (int j = 0; j < 8; j++)
            #pragma unroll
            for (int q = 0; q < 4; q++) acc[i][j][q] = 0.0f;

    ISSUE_CHUNK(0);
    ISSUE_CHUNK(1);

    for (int kc = 0; kc < NCHUNK; kc++) {
        if (kc == NCHUNK - 1) CP_WAIT0(); else CP_WAIT1();
        __syncthreads();
        // This barrier both (a) makes stage kc's data visible to all warps and
        // (b) proves all warps finished reading stage kc-1 => safe to overwrite
        // stage (kc+2)%3 below. No second barrier needed at loop end.

        if (kc + 2 < NCHUNK) ISSUE_CHUNK(kc + 2);

        const int st = kc % NSTAGE;
        const uint32_t sA = S + st * STG;
        const uint32_t sB = sA + TILE_B;

        #pragma unroll
        for (int ks = 0; ks < 4; ks++) {           // 4 x k8 = BK
            uint32_t a[2][4];
            #pragma unroll
            for (int i = 0; i < 2; i++)
                ldsm_x4(a[i][0], a[i][1], a[i][2], a[i][3],
                        sA + SW128(aByte[i] + ks * 32));
            uint32_t b[8][2];
            #pragma unroll
            for (int p = 0; p < 4; p++)
                ldsm_x4(b[2*p][0], b[2*p][1], b[2*p+1][0], b[2*p+1][1],
                        sB + SW128(bByte[p] + ks * 32));
            #pragma unroll
            for (int i = 0; i < 2; i++)
                #pragma unroll
                for (int j = 0; j < 8; j++)
                    mma_tf32(acc[i][j], a[i], b[j]);
        }
    }

    // ---- epilogue: bias + store ----
    const int mrow = m0 + mw + (lane >> 2);
    const int ncol = n0 + nw + (lane & 3) * 2;
    #pragma unroll
    for (int i = 0; i < 2; i++) {
        const int r0 = mrow + i * 16;
        const float b0 = bias[r0];
        const float b1 = bias[r0 + 8];
        float* C0 = g_hg + ((size_t)bz * TWOH + r0)     * Ll;
        float* C1 = g_hg + ((size_t)bz * TWOH + r0 + 8) * Ll;
        #pragma unroll
        for (int j = 0; j < 8; j++) {
            const int c = ncol + j * 8;
            float2 o0 = { acc[i][j][0] + b0, acc[i][j][1] + b0 };
            float2 o1 = { acc[i][j][2] + b1, acc[i][j][3] + b1 };
            *(float2*)(C0 + c) = o0;
            *(float2*)(C1 + c) = o1;
        }
    }
}

// ---------------------------------------------------------------------------
// Scan: one block per (b,h) lane; 2 blocks/SM; fast-math exp. (65.7us in R12)
// ---------------------------------------------------------------------------
__global__ __launch_bounds__(1024, 2)
void scan_kernel(float* __restrict__ out) {
    const int lane_id = blockIdx.x;
    const int b = lane_id >> 9;
    const int h = lane_id & 511;

    const float* Hrow = g_hg + ((size_t)b * TWOH + h)      * Ll;
    const float* Grow = g_hg + ((size_t)b * TWOH + Hh + h) * Ll;
    float*       Orow = out  + (size_t)lane_id * Ll;

    const int t  = threadIdx.x;
    const int l0 = t * 8;

    float4 hA = *(const float4*)(Hrow + l0);
    float4 hB = *(const float4*)(Hrow + l0 + 4);
    float4 gA = *(const float4*)(Grow + l0);
    float4 gB = *(const float4*)(Grow + l0 + 4);

    float hv[8] = {hA.x, hA.y, hA.z, hA.w, hB.x, hB.y, hB.z, hB.w};
    float gv[8] = {gA.x, gA.y, gA.z, gA.w, gB.x, gB.y, gB.z, gB.w};

    float c[8], v[8];
    #pragma unroll
    for (int i = 0; i < 8; i++) {
        const float g  = gv[i];
        const float eg = __expf(g);
        const float ci = 1.0f / (1.0f + eg);          // sigmoid(-g)
        const float si = 1.0f - ci;                   // sigmoid(g)
        const float z  = hv[i];
        const float gf = (z >= 0.0f) ? (z + 1.0f) : __expf(z);
        c[i] = ci;
        v[i] = si * gf;
    }

    float C = c[0], V = v[0];
    #pragma unroll
    for (int i = 1; i < 8; i++) {
        V = fmaf(c[i], V, v[i]);
        C *= c[i];
    }

    const int lane = t & 31, warp = t >> 5;
    #pragma unroll
    for (int d = 1; d < 32; d <<= 1) {
        float Cp = __shfl_up_sync(0xFFFFFFFFu, C, d);
        float Vp = __shfl_up_sync(0xFFFFFFFFu, V, d);
        if (lane >= d) { V = fmaf(C, Vp, V); C = C * Cp; }
    }

    __shared__ float sC[32], sV[32];
    if (lane == 31) { sC[warp] = C; sV[warp] = V; }
    __syncthreads();

    if (warp == 0) {
        float Cw = sC[lane], Vw = sV[lane];
        #pragma unroll
        for (int d = 1; d < 32; d <<= 1) {
            float Cp = __shfl_up_sync(0xFFFFFFFFu, Cw, d);
            float Vp = __shfl_up_sync(0xFFFFFFFFu, Vw, d);
            if (lane >= d) { Vw = fmaf(Cw, Vp, Vw); Cw = Cw * Cp; }
        }
        sC[lane] = Cw;
        sV[lane] = Vw;
    }
    __syncthreads();

    float bV = (warp == 0) ? 0.0f : sV[warp - 1];

    float eC = __shfl_up_sync(0xFFFFFFFFu, C, 1);
    float eV = __shfl_up_sync(0xFFFFFFFFu, V, 1);
    if (lane == 0) { eC = 1.0f; eV = 0.0f; }

    float acc = fmaf(eC, bV, eV);

    float o[8];
    #pragma unroll
    for (int i = 0; i < 8; i++) {
        acc  = fmaf(c[i], acc, v[i]);
        o[i] = acc;
    }
    float4 oA = {o[0], o[1], o[2], o[3]};
    float4 oB = {o[4], o[5], o[6], o[7]};
    *(float4*)(Orow + l0)     = oA;
    *(float4*)(Orow + l0 + 4) = oB;
}

// ---------------------------------------------------------------------------
extern "C" void kernel_launch(void* const* d_in, const int* in_sizes, int n_in,
                              void* d_out, int out_size) {
    const float* x = nullptr;
    const float* W = nullptr;
    const float* bias = nullptr;
    for (int i = 0; i < n_in; i++) {
        const int s = in_sizes[i];
        if      (s == Bsz * Dd * Ll) x    = (const float*)d_in[i];
        else if (s == TWOH * Dd)     W    = (const float*)d_in[i];
        else if (s == TWOH)          bias = (const float*)d_in[i];
    }

    static int smem_set = 0;
    if (!smem_set) {
        cudaFuncSetAttribute(gemm_tc_kernel,
                             cudaFuncAttributeMaxDynamicSharedMemorySize,
                             SMEM_BYTES);
        smem_set = 1;
    }

    round_w_kernel<<<TWOH * Dd / (256 * 4), 256>>>(W);
    trans_x_kernel<<<dim3(Ll / 64, Dd / 64, Bsz), 256>>>(x);
    // m innermost (x), n outer (y): 8 m-CTAs per X n-tile launch-adjacent
    gemm_tc_kernel<<<dim3(TWOH / BM, Ll / BN, Bsz), 256, SMEM_BYTES>>>(bias);
    scan_kernel<<<Bsz * Hh, 1024>>>((float*)d_out);
}

// round 14
// speedup vs baseline: 2.2948x; 1.6247x over previous
#include <cuda_runtime.h>
#include <cuda_fp16.h>
#include <cstdint>
#include <math.h>

// ---------------------------------------------------------------------------
// minGRU forward on GB300 (compute_103 PTX => classic mma.sync tensor path):
//   hg = W @ x + b   via single-pass FP16 m16n8k16 mma.sync GEMM.
//   fp16 mantissa (10 bits) == tf32 mantissa => same accuracy as the tf32
//   version (rel_err 2.13e-4), but 2048 MACs/instr => half the instructions.
//   then per-(b,h) linear scan  h_t = c_t h_{t-1} + v_t   (fast-exp, 2/SM)
// ---------------------------------------------------------------------------

#define Bsz 8
#define Dd  512
#define Hh  512
#define Ll  8192
#define TWOH 1024

// Scratch (device globals: allocation-free path)
__device__ float  g_hg [(size_t)Bsz * TWOH * Ll];   // 268 MB
__device__ __half g_x16[(size_t)Bsz * Ll * Dd];     // 67 MB  [B,L,D] fp16
__device__ __half g_w16[(size_t)TWOH * Dd];         // 1 MB   [2H,D]  fp16

// ---------------------------- PTX helpers ----------------------------------
__device__ __forceinline__ uint32_t smem_u32(const void* p) {
    uint32_t a;
    asm("{ .reg .u64 t; cvta.to.shared.u64 t, %1; cvt.u32.u64 %0, t; }"
        : "=r"(a) : "l"(p));
    return a;
}
#define SW128(o) ((o) ^ (((o) >> 3) & 0x70))

__device__ __forceinline__ void cp16(uint32_t dst, const void* src) {
    asm volatile("cp.async.cg.shared.global [%0], [%1], 16;"
                 :: "r"(dst), "l"(__cvta_generic_to_global(src)) : "memory");
}
#define CP_COMMIT() asm volatile("cp.async.commit_group;" ::: "memory")
#define CP_WAIT0()  asm volatile("cp.async.wait_group 0;" ::: "memory")
#define CP_WAIT1()  asm volatile("cp.async.wait_group 1;" ::: "memory")

__device__ __forceinline__ void ldsm_x4(uint32_t &r0, uint32_t &r1,
                                        uint32_t &r2, uint32_t &r3,
                                        uint32_t addr) {
    asm volatile("ldmatrix.sync.aligned.m8n8.x4.shared.b16 {%0,%1,%2,%3}, [%4];"
                 : "=r"(r0), "=r"(r1), "=r"(r2), "=r"(r3) : "r"(addr));
}

__device__ __forceinline__ void mma_f16(float c[4], const uint32_t a[4],
                                        const uint32_t b[2]) {
    asm volatile(
        "mma.sync.aligned.m16n8k16.row.col.f32.f16.f16.f32 "
        "{%0,%1,%2,%3}, {%4,%5,%6,%7}, {%8,%9}, {%0,%1,%2,%3};"
        : "+f"(c[0]), "+f"(c[1]), "+f"(c[2]), "+f"(c[3])
        : "r"(a[0]), "r"(a[1]), "r"(a[2]), "r"(a[3]), "r"(b[0]), "r"(b[1]));
}

// ---------------------------------------------------------------------------
// Prep kernels: W -> fp16; transpose X [B,D,L] -> [B,L,D] fp16
// ---------------------------------------------------------------------------
__global__ void conv_w_kernel(const float* __restrict__ W) {
    int i = (blockIdx.x * 256 + threadIdx.x) * 4;
    float4 v = *(const float4*)(W + i);
    uint32_t p0 = (uint32_t)__half_as_ushort(__float2half_rn(v.x)) |
                  ((uint32_t)__half_as_ushort(__float2half_rn(v.y)) << 16);
    uint32_t p1 = (uint32_t)__half_as_ushort(__float2half_rn(v.z)) |
                  ((uint32_t)__half_as_ushort(__float2half_rn(v.w)) << 16);
    *(uint2*)&g_w16[i] = make_uint2(p0, p1);
}

__global__ __launch_bounds__(256)
void trans_x_kernel(const float* __restrict__ X) {
    __shared__ float ts[64 * 65];
    const int b  = blockIdx.z;
    const int d0 = blockIdx.y * 64;
    const int l0 = blockIdx.x * 64;
    const int t  = threadIdx.x;

    {
        const int dl = t >> 2;
        const int lc = (t & 3) * 16;
        const float* src = X + ((size_t)b * Dd + d0 + dl) * Ll + l0 + lc;
        #pragma unroll
        for (int j = 0; j < 4; j++) {
            float4 v = *(const float4*)(src + j * 4);
            ts[dl * 65 + lc + j * 4 + 0] = v.x;
            ts[dl * 65 + lc + j * 4 + 1] = v.y;
            ts[dl * 65 + lc + j * 4 + 2] = v.z;
            ts[dl * 65 + lc + j * 4 + 3] = v.w;
        }
    }
    __syncthreads();

    const int ll = t >> 2;
    const int dc = (t & 3) * 16;
    __half* dst = g_x16 + ((size_t)b * Ll + l0 + ll) * Dd + d0 + dc;
    #pragma unroll
    for (int h = 0; h < 2; h++) {
        uint32_t p[4];
        #pragma unroll
        for (int q = 0; q < 4; q++) {
            float x0 = ts[(dc + h * 8 + 2 * q + 0) * 65 + ll];
            float x1 = ts[(dc + h * 8 + 2 * q + 1) * 65 + ll];
            p[q] = (uint32_t)__half_as_ushort(__float2half_rn(x0)) |
                   ((uint32_t)__half_as_ushort(__float2half_rn(x1)) << 16);
        }
        *(uint4*)(dst + h * 8) = make_uint4(p[0], p[1], p[2], p[3]);
    }
}

// ---------------------------------------------------------------------------
// FP16 mma.sync GEMM: C[b](1024 x 8192) = W(1024x512) @ X[b]^T + bias
// BM=128, BN=128, BK=64 fp16 elems (128B rows), 3-stage cp.async pipeline,
// SW128 swizzle, 8 warps (4M x 2N), warp tile 32x64, 2 CTAs/SM.
// Single barrier per k-chunk (stage reuse ordered by top-of-iteration sync).
// ---------------------------------------------------------------------------
#define BM 128
#define BN 128
#define BK 64
#define NCHUNK (Dd / BK)       // 8
#define NSTAGE 3
#define TILE_B (BM * 128)      // 16 KB per operand tile (128B rows)
#define STG    (2 * TILE_B)    // A + B per stage = 32 KB
#define SMEM_BYTES (NSTAGE * STG + 1024)   // 99328

__global__ __launch_bounds__(256, 2)
void gemm_tc_kernel(const float* __restrict__ bias) {
    extern __shared__ char dynsmem[];
    const uint32_t S = (smem_u32(dynsmem) + 1023u) & ~1023u;

    const int tid  = threadIdx.x;
    const int wid  = tid >> 5;
    const int lane = tid & 31;
    const int bz = blockIdx.z;
    const int m0 = blockIdx.x * BM;     // m innermost (8 tiles): L2 reuse of X
    const int n0 = blockIdx.y * BN;

    // ---- load mapping: 2 threads per 128B row, 4x cp16 each per operand ----
    const int lrow  = tid >> 1;           // 0..127
    const int lhalf = (tid & 1) * 4;      // 0 or 4

    const __half* srcA = g_w16 + (size_t)(m0 + lrow) * Dd;
    const __half* srcB = g_x16 + ((size_t)bz * Ll + n0 + lrow) * Dd;

    #define ISSUE_CHUNK(kc)                                                     \
    do {                                                                        \
        const int _st = (kc) % NSTAGE;                                          \
        const uint32_t _sA = S + _st * STG;                                     \
        const uint32_t _sB = _sA + TILE_B;                                      \
        const int _kb = (kc) * 128;  /* BK*2 bytes into the source row */       \
        _Pragma("unroll")                                                       \
        for (int j = 0; j < 4; j++) {                                           \
            const int jj = lhalf + j;                                           \
            const uint32_t so = SW128((uint32_t)(lrow * 128 + jj * 16));        \
            cp16(_sA + so, (const char*)srcA + _kb + jj * 16);                  \
            cp16(_sB + so, (const char*)srcB + _kb + jj * 16);                  \
        }                                                                       \
        CP_COMMIT();                                                            \
    } while (0)

    // ---- fragment lane addressing (k16 b16 mapping, proven in R7) ----
    const int mw = (wid & 3) * 32;        // warp M offset
    const int nw = (wid >> 2) * 64;       // warp N offset
    // A x4: (m0-7,k0-7),(m8-15,k0-7),(m0-7,k8-15),(m8-15,k8-15)
    const int aRow = ((lane >> 3) & 1) * 8 + (lane & 7);
    const int aCol = (lane >> 4) * 16;    // byte offset (8 fp16)
    // B x4: (n0-7,k0-7),(n0-7,k8-15),(n8-15,k0-7),(n8-15,k8-15)
    const int bRow = (lane >> 4) * 8 + (lane & 7);
    const int bCol = ((lane >> 3) & 1) * 16;

    uint32_t aByte[2], bByte[4];
    #pragma unroll
    for (int i = 0; i < 2; i++)
        aByte[i] = (uint32_t)((mw + i * 16 + aRow) * 128 + aCol);
    #pragma unroll
    for (int p = 0; p < 4; p++)
        bByte[p] = (uint32_t)((nw + p * 16 + bRow) * 128 + bCol);

    float acc[2][8][4];
    #pragma unroll
    for (int i = 0; i < 2; i++)
        #pragma unroll
        for (int j = 0; j < 8; j++)
            #pragma unroll
            for (int q = 0; q < 4; q++) acc[i][j][q] = 0.0f;

    ISSUE_CHUNK(0);
    ISSUE_CHUNK(1);

    for (int kc = 0; kc < NCHUNK; kc++) {
        if (kc == NCHUNK - 1) CP_WAIT0(); else CP_WAIT1();
        __syncthreads();
        // Single barrier: makes stage kc visible AND proves stage kc-1 fully
        // consumed => safe to overwrite stage (kc+2)%3 below.

        if (kc + 2 < NCHUNK) ISSUE_CHUNK(kc + 2);

        const int st = kc % NSTAGE;
        const uint32_t sA = S + st * STG;
        const uint32_t sB = sA + TILE_B;

        #pragma unroll
        for (int ks = 0; ks < 4; ks++) {           // 4 x k16 = BK=64
            uint32_t a[2][4];
            #pragma unroll
            for (int i = 0; i < 2; i++)
                ldsm_x4(a[i][0], a[i][1], a[i][2], a[i][3],
                        sA + SW128(aByte[i] + ks * 32));
            uint32_t b[8][2];
            #pragma unroll
            for (int p = 0; p < 4; p++)
                ldsm_x4(b[2*p][0], b[2*p][1], b[2*p+1][0], b[2*p+1][1],
                        sB + SW128(bByte[p] + ks * 32));
            #pragma unroll
            for (int i = 0; i < 2; i++)
                #pragma unroll
                for (int j = 0; j < 8; j++)
                    mma_f16(acc[i][j], a[i], b[j]);
        }
    }

    // ---- epilogue: bias + store ----
    const int mrow = m0 + mw + (lane >> 2);
    const int ncol = n0 + nw + (lane & 3) * 2;
    #pragma unroll
    for (int i = 0; i < 2; i++) {
        const int r0 = mrow + i * 16;
        const float b0 = bias[r0];
        const float b1 = bias[r0 + 8];
        float* C0 = g_hg + ((size_t)bz * TWOH + r0)     * Ll;
        float* C1 = g_hg + ((size_t)bz * TWOH + r0 + 8) * Ll;
        #pragma unroll
        for (int j = 0; j < 8; j++) {
            const int c = ncol + j * 8;
            float2 o0 = { acc[i][j][0] + b0, acc[i][j][1] + b0 };
            float2 o1 = { acc[i][j][2] + b1, acc[i][j][3] + b1 };
            *(float2*)(C0 + c) = o0;
            *(float2*)(C1 + c) = o1;
        }
    }
}

// ---------------------------------------------------------------------------
// Scan: one block per (b,h) lane; 2 blocks/SM; fast-math exp. (66us proven)
// ---------------------------------------------------------------------------
__global__ __launch_bounds__(1024, 2)
void scan_kernel(float* __restrict__ out) {
    const int lane_id = blockIdx.x;
    const int b = lane_id >> 9;
    const int h = lane_id & 511;

    const float* Hrow = g_hg + ((size_t)b * TWOH + h)      * Ll;
    const float* Grow = g_hg + ((size_t)b * TWOH + Hh + h) * Ll;
    float*       Orow = out  + (size_t)lane_id * Ll;

    const int t  = threadIdx.x;
    const int l0 = t * 8;

    float4 hA = *(const float4*)(Hrow + l0);
    float4 hB = *(const float4*)(Hrow + l0 + 4);
    float4 gA = *(const float4*)(Grow + l0);
    float4 gB = *(const float4*)(Grow + l0 + 4);

    float hv[8] = {hA.x, hA.y, hA.z, hA.w, hB.x, hB.y, hB.z, hB.w};
    float gv[8] = {gA.x, gA.y, gA.z, gA.w, gB.x, gB.y, gB.z, gB.w};

    float c[8], v[8];
    #pragma unroll
    for (int i = 0; i < 8; i++) {
        const float g  = gv[i];
        const float eg = __expf(g);
        const float ci = 1.0f / (1.0f + eg);          // sigmoid(-g)
        const float si = 1.0f - ci;                   // sigmoid(g)
        const float z  = hv[i];
        const float gf = (z >= 0.0f) ? (z + 1.0f) : __expf(z);
        c[i] = ci;
        v[i] = si * gf;
    }

    float C = c[0], V = v[0];
    #pragma unroll
    for (int i = 1; i < 8; i++) {
        V = fmaf(c[i], V, v[i]);
        C *= c[i];
    }

    const int lane = t & 31, warp = t >> 5;
    #pragma unroll
    for (int d = 1; d < 32; d <<= 1) {
        float Cp = __shfl_up_sync(0xFFFFFFFFu, C, d);
        float Vp = __shfl_up_sync(0xFFFFFFFFu, V, d);
        if (lane >= d) { V = fmaf(C, Vp, V); C = C * Cp; }
    }

    __shared__ float sC[32], sV[32];
    if (lane == 31) { sC[warp] = C; sV[warp] = V; }
    __syncthreads();

    if (warp == 0) {
        float Cw = sC[lane], Vw = sV[lane];
        #pragma unroll
        for (int d = 1; d < 32; d <<= 1) {
            float Cp = __shfl_up_sync(0xFFFFFFFFu, Cw, d);
            float Vp = __shfl_up_sync(0xFFFFFFFFu, Vw, d);
            if (lane >= d) { Vw = fmaf(Cw, Vp, Vw); Cw = Cw * Cp; }
        }
        sC[lane] = Cw;
        sV[lane] = Vw;
    }
    __syncthreads();

    float bV = (warp == 0) ? 0.0f : sV[warp - 1];

    float eC = __shfl_up_sync(0xFFFFFFFFu, C, 1);
    float eV = __shfl_up_sync(0xFFFFFFFFu, V, 1);
    if (lane == 0) { eC = 1.0f; eV = 0.0f; }

    float acc = fmaf(eC, bV, eV);

    float o[8];
    #pragma unroll
    for (int i = 0; i < 8; i++) {
        acc  = fmaf(c[i], acc, v[i]);
        o[i] = acc;
    }
    float4 oA = {o[0], o[1], o[2], o[3]};
    float4 oB = {o[4], o[5], o[6], o[7]};
    *(float4*)(Orow + l0)     = oA;
    *(float4*)(Orow + l0 + 4) = oB;
}

// ---------------------------------------------------------------------------
extern "C" void kernel_launch(void* const* d_in, const int* in_sizes, int n_in,
                              void* d_out, int out_size) {
    const float* x = nullptr;
    const float* W = nullptr;
    const float* bias = nullptr;
    for (int i = 0; i < n_in; i++) {
        const int s = in_sizes[i];
        if      (s == Bsz * Dd * Ll) x    = (const float*)d_in[i];
        else if (s == TWOH * Dd)     W    = (const float*)d_in[i];
        else if (s == TWOH)          bias = (const float*)d_in[i];
    }

    static int smem_set = 0;
    if (!smem_set) {
        cudaFuncSetAttribute(gemm_tc_kernel,
                             cudaFuncAttributeMaxDynamicSharedMemorySize,
                             SMEM_BYTES);
        smem_set = 1;
    }

    conv_w_kernel<<<TWOH * Dd / (256 * 4), 256>>>(W);
    trans_x_kernel<<<dim3(Ll / 64, Dd / 64, Bsz), 256>>>(x);
    gemm_tc_kernel<<<dim3(TWOH / BM, Ll / BN, Bsz), 256, SMEM_BYTES>>>(bias);
    scan_kernel<<<Bsz * Hh, 1024>>>((float*)d_out);
}

// round 15
// speedup vs baseline: 2.3116x; 1.0073x over previous
#include <cuda_runtime.h>
#include <cuda_fp16.h>
#include <cstdint>
#include <math.h>

// ---------------------------------------------------------------------------
// minGRU forward on GB300 (compute_103 PTX => classic mma.sync tensor path):
//   hg = W @ x + b   via single-pass FP16 m16n8k16 mma.sync GEMM (at the
//                    legacy-HMMA issue floor, rt~16/SMSP).
//   hg intermediate stored as fp16 (halves the scratch round-trip; adds one
//   2^-12-mean rounding, est. total rel_err ~3.2e-4 vs 1e-3 gate).
//   then per-(b,h) linear scan  h_t = c_t h_{t-1} + v_t   (fast-exp, 2/SM)
// ---------------------------------------------------------------------------

#define Bsz 8
#define Dd  512
#define Hh  512
#define Ll  8192
#define TWOH 1024

// Scratch (device globals: allocation-free path)
__device__ __half g_hg [(size_t)Bsz * TWOH * Ll];   // 134 MB  fp16 h|gate
__device__ __half g_x16[(size_t)Bsz * Ll * Dd];     // 67 MB   [B,L,D] fp16
__device__ __half g_w16[(size_t)TWOH * Dd];         // 1 MB    [2H,D]  fp16

// ---------------------------- PTX helpers ----------------------------------
__device__ __forceinline__ uint32_t smem_u32(const void* p) {
    uint32_t a;
    asm("{ .reg .u64 t; cvta.to.shared.u64 t, %1; cvt.u32.u64 %0, t; }"
        : "=r"(a) : "l"(p));
    return a;
}
#define SW128(o) ((o) ^ (((o) >> 3) & 0x70))

__device__ __forceinline__ void cp16(uint32_t dst, const void* src) {
    asm volatile("cp.async.cg.shared.global [%0], [%1], 16;"
                 :: "r"(dst), "l"(__cvta_generic_to_global(src)) : "memory");
}
#define CP_COMMIT() asm volatile("cp.async.commit_group;" ::: "memory")
#define CP_WAIT0()  asm volatile("cp.async.wait_group 0;" ::: "memory")
#define CP_WAIT1()  asm volatile("cp.async.wait_group 1;" ::: "memory")

__device__ __forceinline__ void ldsm_x4(uint32_t &r0, uint32_t &r1,
                                        uint32_t &r2, uint32_t &r3,
                                        uint32_t addr) {
    asm volatile("ldmatrix.sync.aligned.m8n8.x4.shared.b16 {%0,%1,%2,%3}, [%4];"
                 : "=r"(r0), "=r"(r1), "=r"(r2), "=r"(r3) : "r"(addr));
}

__device__ __forceinline__ void mma_f16(float c[4], const uint32_t a[4],
                                        const uint32_t b[2]) {
    asm volatile(
        "mma.sync.aligned.m16n8k16.row.col.f32.f16.f16.f32 "
        "{%0,%1,%2,%3}, {%4,%5,%6,%7}, {%8,%9}, {%0,%1,%2,%3};"
        : "+f"(c[0]), "+f"(c[1]), "+f"(c[2]), "+f"(c[3])
        : "r"(a[0]), "r"(a[1]), "r"(a[2]), "r"(a[3]), "r"(b[0]), "r"(b[1]));
}

// ---------------------------------------------------------------------------
// Prep kernels: W -> fp16; transpose X [B,D,L] -> [B,L,D] fp16
// ---------------------------------------------------------------------------
__global__ void conv_w_kernel(const float* __restrict__ W) {
    int i = (blockIdx.x * 256 + threadIdx.x) * 4;
    float4 v = *(const float4*)(W + i);
    uint32_t p0 = (uint32_t)__half_as_ushort(__float2half_rn(v.x)) |
                  ((uint32_t)__half_as_ushort(__float2half_rn(v.y)) << 16);
    uint32_t p1 = (uint32_t)__half_as_ushort(__float2half_rn(v.z)) |
                  ((uint32_t)__half_as_ushort(__float2half_rn(v.w)) << 16);
    *(uint2*)&g_w16[i] = make_uint2(p0, p1);
}

__global__ __launch_bounds__(256)
void trans_x_kernel(const float* __restrict__ X) {
    __shared__ float ts[64 * 65];
    const int b  = blockIdx.z;
    const int d0 = blockIdx.y * 64;
    const int l0 = blockIdx.x * 64;
    const int t  = threadIdx.x;

    {
        const int dl = t >> 2;
        const int lc = (t & 3) * 16;
        const float* src = X + ((size_t)b * Dd + d0 + dl) * Ll + l0 + lc;
        #pragma unroll
        for (int j = 0; j < 4; j++) {
            float4 v = *(const float4*)(src + j * 4);
            ts[dl * 65 + lc + j * 4 + 0] = v.x;
            ts[dl * 65 + lc + j * 4 + 1] = v.y;
            ts[dl * 65 + lc + j * 4 + 2] = v.z;
            ts[dl * 65 + lc + j * 4 + 3] = v.w;
        }
    }
    __syncthreads();

    const int ll = t >> 2;
    const int dc = (t & 3) * 16;
    __half* dst = g_x16 + ((size_t)b * Ll + l0 + ll) * Dd + d0 + dc;
    #pragma unroll
    for (int h = 0; h < 2; h++) {
        uint32_t p[4];
        #pragma unroll
        for (int q = 0; q < 4; q++) {
            float x0 = ts[(dc + h * 8 + 2 * q + 0) * 65 + ll];
            float x1 = ts[(dc + h * 8 + 2 * q + 1) * 65 + ll];
            p[q] = (uint32_t)__half_as_ushort(__float2half_rn(x0)) |
                   ((uint32_t)__half_as_ushort(__float2half_rn(x1)) << 16);
        }
        *(uint4*)(dst + h * 8) = make_uint4(p[0], p[1], p[2], p[3]);
    }
}

// ---------------------------------------------------------------------------
// FP16 mma.sync GEMM: C[b](1024 x 8192) = W(1024x512) @ X[b]^T + bias
// BM=128, BN=128, BK=64 fp16 elems (128B rows), 3-stage cp.async pipeline,
// SW128 swizzle, 8 warps (4M x 2N), warp tile 32x64, 2 CTAs/SM.
// Output stored as packed fp16 (half2 stores).
// ---------------------------------------------------------------------------
#define BM 128
#define BN 128
#define BK 64
#define NCHUNK (Dd / BK)       // 8
#define NSTAGE 3
#define TILE_B (BM * 128)      // 16 KB per operand tile (128B rows)
#define STG    (2 * TILE_B)    // A + B per stage = 32 KB
#define SMEM_BYTES (NSTAGE * STG + 1024)   // 99328

__global__ __launch_bounds__(256, 2)
void gemm_tc_kernel(const float* __restrict__ bias) {
    extern __shared__ char dynsmem[];
    const uint32_t S = (smem_u32(dynsmem) + 1023u) & ~1023u;

    const int tid  = threadIdx.x;
    const int wid  = tid >> 5;
    const int lane = tid & 31;
    const int bz = blockIdx.z;
    const int m0 = blockIdx.x * BM;     // m innermost (8 tiles): L2 reuse of X
    const int n0 = blockIdx.y * BN;

    // ---- load mapping: 2 threads per 128B row, 4x cp16 each per operand ----
    const int lrow  = tid >> 1;           // 0..127
    const int lhalf = (tid & 1) * 4;      // 0 or 4

    const __half* srcA = g_w16 + (size_t)(m0 + lrow) * Dd;
    const __half* srcB = g_x16 + ((size_t)bz * Ll + n0 + lrow) * Dd;

    #define ISSUE_CHUNK(kc)                                                     \
    do {                                                                        \
        const int _st = (kc) % NSTAGE;                                          \
        const uint32_t _sA = S + _st * STG;                                     \
        const uint32_t _sB = _sA + TILE_B;                                      \
        const int _kb = (kc) * 128;  /* BK*2 bytes into the source row */       \
        _Pragma("unroll")                                                       \
        for (int j = 0; j < 4; j++) {                                           \
            const int jj = lhalf + j;                                           \
            const uint32_t so = SW128((uint32_t)(lrow * 128 + jj * 16));        \
            cp16(_sA + so, (const char*)srcA + _kb + jj * 16);                  \
            cp16(_sB + so, (const char*)srcB + _kb + jj * 16);                  \
        }                                                                       \
        CP_COMMIT();                                                            \
    } while (0)

    // ---- fragment lane addressing (k16 b16 mapping, proven R7/R14) ----
    const int mw = (wid & 3) * 32;        // warp M offset
    const int nw = (wid >> 2) * 64;       // warp N offset
    const int aRow = ((lane >> 3) & 1) * 8 + (lane & 7);
    const int aCol = (lane >> 4) * 16;    // byte offset (8 fp16)
    const int bRow = (lane >> 4) * 8 + (lane & 7);
    const int bCol = ((lane >> 3) & 1) * 16;

    uint32_t aByte[2], bByte[4];
    #pragma unroll
    for (int i = 0; i < 2; i++)
        aByte[i] = (uint32_t)((mw + i * 16 + aRow) * 128 + aCol);
    #pragma unroll
    for (int p = 0; p < 4; p++)
        bByte[p] = (uint32_t)((nw + p * 16 + bRow) * 128 + bCol);

    float acc[2][8][4];
    #pragma unroll
    for (int i = 0; i < 2; i++)
        #pragma unroll
        for (int j = 0; j < 8; j++)
            #pragma unroll
            for (int q = 0; q < 4; q++) acc[i][j][q] = 0.0f;

    ISSUE_CHUNK(0);
    ISSUE_CHUNK(1);

    for (int kc = 0; kc < NCHUNK; kc++) {
        if (kc == NCHUNK - 1) CP_WAIT0(); else CP_WAIT1();
        __syncthreads();
        // Single barrier: makes stage kc visible AND proves stage kc-1 fully
        // consumed => safe to overwrite stage (kc+2)%3 below.

        if (kc + 2 < NCHUNK) ISSUE_CHUNK(kc + 2);

        const int st = kc % NSTAGE;
        const uint32_t sA = S + st * STG;
        const uint32_t sB = sA + TILE_B;

        #pragma unroll
        for (int ks = 0; ks < 4; ks++) {           // 4 x k16 = BK=64
            uint32_t a[2][4];
            #pragma unroll
            for (int i = 0; i < 2; i++)
                ldsm_x4(a[i][0], a[i][1], a[i][2], a[i][3],
                        sA + SW128(aByte[i] + ks * 32));
            uint32_t b[8][2];
            #pragma unroll
            for (int p = 0; p < 4; p++)
                ldsm_x4(b[2*p][0], b[2*p][1], b[2*p+1][0], b[2*p+1][1],
                        sB + SW128(bByte[p] + ks * 32));
            #pragma unroll
            for (int i = 0; i < 2; i++)
                #pragma unroll
                for (int j = 0; j < 8; j++)
                    mma_f16(acc[i][j], a[i], b[j]);
        }
    }

    // ---- epilogue: bias + packed fp16 store ----
    const int mrow = m0 + mw + (lane >> 2);
    const int ncol = n0 + nw + (lane & 3) * 2;
    #pragma unroll
    for (int i = 0; i < 2; i++) {
        const int r0 = mrow + i * 16;
        const float b0 = bias[r0];
        const float b1 = bias[r0 + 8];
        __half* C0 = g_hg + ((size_t)bz * TWOH + r0)     * Ll;
        __half* C1 = g_hg + ((size_t)bz * TWOH + r0 + 8) * Ll;
        #pragma unroll
        for (int j = 0; j < 8; j++) {
            const int c = ncol + j * 8;
            __half2 p0 = __floats2half2_rn(acc[i][j][0] + b0, acc[i][j][1] + b0);
            __half2 p1 = __floats2half2_rn(acc[i][j][2] + b1, acc[i][j][3] + b1);
            *(__half2*)(C0 + c) = p0;
            *(__half2*)(C1 + c) = p1;
        }
    }
}

// ---------------------------------------------------------------------------
// Scan: one block per (b,h) lane; 2 blocks/SM; fp16 hg reads, fast-math exp.
// ---------------------------------------------------------------------------
__global__ __launch_bounds__(1024, 2)
void scan_kernel(float* __restrict__ out) {
    const int lane_id = blockIdx.x;
    const int b = lane_id >> 9;
    const int h = lane_id & 511;

    const __half* Hrow = g_hg + ((size_t)b * TWOH + h)      * Ll;
    const __half* Grow = g_hg + ((size_t)b * TWOH + Hh + h) * Ll;
    float*        Orow = out  + (size_t)lane_id * Ll;

    const int t  = threadIdx.x;
    const int l0 = t * 8;

    // 8 halves = one uint4 per operand
    uint4 hraw = *(const uint4*)(Hrow + l0);
    uint4 graw = *(const uint4*)(Grow + l0);

    float hv[8], gv[8];
    {
        const uint32_t* hp = (const uint32_t*)&hraw;
        const uint32_t* gp = (const uint32_t*)&graw;
        #pragma unroll
        for (int q = 0; q < 4; q++) {
            float2 hf = __half22float2(*(const __half2*)&hp[q]);
            float2 gf = __half22float2(*(const __half2*)&gp[q]);
            hv[2*q]   = hf.x; hv[2*q+1] = hf.y;
            gv[2*q]   = gf.x; gv[2*q+1] = gf.y;
        }
    }

    float c[8], v[8];
    #pragma unroll
    for (int i = 0; i < 8; i++) {
        const float g  = gv[i];
        const float eg = __expf(g);
        const float ci = 1.0f / (1.0f + eg);          // sigmoid(-g)
        const float si = 1.0f - ci;                   // sigmoid(g)
        const float z  = hv[i];
        const float gf = (z >= 0.0f) ? (z + 1.0f) : __expf(z);
        c[i] = ci;
        v[i] = si * gf;
    }

    float C = c[0], V = v[0];
    #pragma unroll
    for (int i = 1; i < 8; i++) {
        V = fmaf(c[i], V, v[i]);
        C *= c[i];
    }

    const int lane = t & 31, warp = t >> 5;
    #pragma unroll
    for (int d = 1; d < 32; d <<= 1) {
        float Cp = __shfl_up_sync(0xFFFFFFFFu, C, d);
        float Vp = __shfl_up_sync(0xFFFFFFFFu, V, d);
        if (lane >= d) { V = fmaf(C, Vp, V); C = C * Cp; }
    }

    __shared__ float sC[32], sV[32];
    if (lane == 31) { sC[warp] = C; sV[warp] = V; }
    __syncthreads();

    if (warp == 0) {
        float Cw = sC[lane], Vw = sV[lane];
        #pragma unroll
        for (int d = 1; d < 32; d <<= 1) {
            float Cp = __shfl_up_sync(0xFFFFFFFFu, Cw, d);
            float Vp = __shfl_up_sync(0xFFFFFFFFu, Vw, d);
            if (lane >= d) { Vw = fmaf(Cw, Vp, Vw); Cw = Cw * Cp; }
        }
        sC[lane] = Cw;
        sV[lane] = Vw;
    }
    __syncthreads();

    float bV = (warp == 0) ? 0.0f : sV[warp - 1];

    float eC = __shfl_up_sync(0xFFFFFFFFu, C, 1);
    float eV = __shfl_up_sync(0xFFFFFFFFu, V, 1);
    if (lane == 0) { eC = 1.0f; eV = 0.0f; }

    float acc = fmaf(eC, bV, eV);

    float o[8];
    #pragma unroll
    for (int i = 0; i < 8; i++) {
        acc  = fmaf(c[i], acc, v[i]);
        o[i] = acc;
    }
    float4 oA = {o[0], o[1], o[2], o[3]};
    float4 oB = {o[4], o[5], o[6], o[7]};
    *(float4*)(Orow + l0)     = oA;
    *(float4*)(Orow + l0 + 4) = oB;
}

// ---------------------------------------------------------------------------
extern "C" void kernel_launch(void* const* d_in, const int* in_sizes, int n_in,
                              void* d_out, int out_size) {
    const float* x = nullptr;
    const float* W = nullptr;
    const float* bias = nullptr;
    for (int i = 0; i < n_in; i++) {
        const int s = in_sizes[i];
        if      (s == Bsz * Dd * Ll) x    = (const float*)d_in[i];
        else if (s == TWOH * Dd)     W    = (const float*)d_in[i];
        else if (s == TWOH)          bias = (const float*)d_in[i];
    }

    static int smem_set = 0;
    if (!smem_set) {
        cudaFuncSetAttribute(gemm_tc_kernel,
                             cudaFuncAttributeMaxDynamicSharedMemorySize,
                             SMEM_BYTES);
        smem_set = 1;
    }

    conv_w_kernel<<<TWOH * Dd / (256 * 4), 256>>>(W);
    trans_x_kernel<<<dim3(Ll / 64, Dd / 64, Bsz), 256>>>(x);
    gemm_tc_kernel<<<dim3(TWOH / BM, Ll / BN, Bsz), 256, SMEM_BYTES>>>(bias);
    scan_kernel<<<Bsz * Hh, 1024>>>((float*)d_out);
}